// round 14
// baseline (speedup 1.0000x reference)
#include <cuda_runtime.h>
#include <cooperative_groups.h>
#include <math.h>

namespace cg = cooperative_groups;

// Problem constants (fixed shapes)
#define S_LEN 2048
#define B_SZ  64
#define H_DIM 1024
#define D_HALF 64
#define W_WIN 129            // 2*D+1
#define DCH   64             // d-chunk for GEMM partial
#define NDC   (H_DIM / DCH)  // 16
#define NT    512            // fused kernel threads (16 warps; reg cap 128)

// Scratch (allocation-free)
__device__ float g_dotp[NDC * B_SZ * H_DIM];   // [dc][b][h]  4 MB

// ---- packed f32x2 helpers (FFMA2: 2x fp32 FMA throughput, same rounding) ----
__device__ __forceinline__ unsigned long long pk2(float lo, float hi) {
    unsigned long long r;
    asm("mov.b64 %0, {%1, %2};" : "=l"(r) : "f"(lo), "f"(hi));
    return r;
}
__device__ __forceinline__ void fma2(unsigned long long& d,
                                     unsigned long long a, unsigned long long b) {
    asm("fma.rn.f32x2 %0, %1, %2, %0;" : "+l"(d) : "l"(a), "l"(b));
}
__device__ __forceinline__ void upk2(unsigned long long v, float& lo, float& hi) {
    asm("mov.b64 {%0, %1}, %2;" : "=f"(lo), "=f"(hi) : "l"(v));
}

// ---------------------------------------------------------------------------
// K1: partial GEMM via FFMA2.  dotp[dc][b][h] = sum_d hidden[b][d]*Wp_w[h][d]
// fp32 semantics preserved exactly: p feeds round() -> window center.
// ---------------------------------------------------------------------------
__global__ __launch_bounds__(256, 2)
void k_gemm_partial(const float* __restrict__ hidden,
                    const float* __restrict__ Wp_w) {
    const int h0 = blockIdx.x * 64;
    const int dc = blockIdx.y;
    const int d0 = dc * DCH;

    __shared__ float sh_ht[DCH][66];  // [d][b] padded (b contiguous)
    __shared__ float sh_w[DCH][65];   // [d][h] padded

    const int tid  = threadIdx.x;
    const int lane = tid & 31;
    const int warp = tid >> 5;

    for (int idx = tid; idx < 64 * 16; idx += 256) {
        int b  = idx >> 4;
        int dq = (idx & 15) << 2;
        float4 v = *reinterpret_cast<const float4*>(&hidden[b * H_DIM + d0 + dq]);
        sh_ht[dq + 0][b] = v.x; sh_ht[dq + 1][b] = v.y;
        sh_ht[dq + 2][b] = v.z; sh_ht[dq + 3][b] = v.w;
    }
    for (int idx = tid; idx < 64 * 16; idx += 256) {
        int h  = idx >> 4;
        int dq = (idx & 15) << 2;
        float4 v = *reinterpret_cast<const float4*>(&Wp_w[(size_t)(h0 + h) * H_DIM + d0 + dq]);
        sh_w[dq + 0][h] = v.x; sh_w[dq + 1][h] = v.y;
        sh_w[dq + 2][h] = v.z; sh_w[dq + 3][h] = v.w;
    }
    __syncthreads();

    const int hl = lane & 15;
    const int bl = ((lane >> 4) << 2) + (warp << 3);   // multiple of 4 -> LDS.64 aligned

    unsigned long long acc2[2][4] = {};
#pragma unroll 16
    for (int d = 0; d < DCH; ++d) {
        float wv0 = sh_w[d][hl];
        float wv1 = sh_w[d][hl + 16];
        float wv2 = sh_w[d][hl + 32];
        float wv3 = sh_w[d][hl + 48];
        unsigned long long wp0 = pk2(wv0, wv0);
        unsigned long long wp1 = pk2(wv1, wv1);
        unsigned long long wp2 = pk2(wv2, wv2);
        unsigned long long wp3 = pk2(wv3, wv3);
        unsigned long long h01 = *reinterpret_cast<const unsigned long long*>(&sh_ht[d][bl]);
        unsigned long long h23 = *reinterpret_cast<const unsigned long long*>(&sh_ht[d][bl + 2]);
        fma2(acc2[0][0], h01, wp0); fma2(acc2[0][1], h01, wp1);
        fma2(acc2[0][2], h01, wp2); fma2(acc2[0][3], h01, wp3);
        fma2(acc2[1][0], h23, wp0); fma2(acc2[1][1], h23, wp1);
        fma2(acc2[1][2], h23, wp2); fma2(acc2[1][3], h23, wp3);
    }

    float* outp = &g_dotp[(size_t)dc * (B_SZ * H_DIM)];
#pragma unroll
    for (int r = 0; r < 2; ++r) {
#pragma unroll
        for (int i = 0; i < 4; ++i) {
            float lo, hi;
            upk2(acc2[r][i], lo, hi);
            int h = h0 + hl + 16 * i;
            outp[(bl + 2 * r + 0) * H_DIM + h] = lo;
            outp[(bl + 2 * r + 1) * H_DIM + h] = hi;
        }
    }
}

// ---------------------------------------------------------------------------
// K2 (fused, clustered, flash + cp.async smem pipeline): 2 CTAs per b,
// 128 blocks, 512 threads. Per-warp 2-slot smem ring: next row streams
// GMEM->SMEM via cp.async (zero register cost) while current row computes.
// ring[0] is reused as the combine buffer after the flash phase.
// ---------------------------------------------------------------------------
struct DynSmem {
    float4 ring[16][2][256];   // per-warp 2-slot row ring   (128 KB)
    float4 ctxw[16][256];      // per-warp ctx accumulators   (64 KB)
    float  hid[H_DIM];         // hidden row                   (4 KB)
    float  scores[W_WIN];
    float  gauss[W_WIN];
    float  m[16];
    float  l[16];
    float  ef[16];
    float  wred[16];
    float  part;
    float  p;
    int    c;
    float  Mrank;
    float  lrank;
};

__device__ __forceinline__ void cp_async16(uint32_t smem_addr, const void* gptr) {
    asm volatile("cp.async.cg.shared.global [%0], [%1], 16;"
                 :: "r"(smem_addr), "l"(gptr) : "memory");
}
__device__ __forceinline__ void cp_async_commit() {
    asm volatile("cp.async.commit_group;" ::: "memory");
}
template <int N>
__device__ __forceinline__ void cp_async_wait() {
    asm volatile("cp.async.wait_group %0;" :: "n"(N) : "memory");
}

__global__ __launch_bounds__(NT, 1) __cluster_dims__(2, 1, 1)
void k_attn_fused(const float* __restrict__ hidden,
                  const float* __restrict__ enc,
                  const float* __restrict__ Wp_b,
                  const float* __restrict__ vp_w,
                  const float* __restrict__ vp_b,
                  float* __restrict__ d_out) {
    cg::cluster_group cluster = cg::this_cluster();
    extern __shared__ __align__(16) char dsm_raw[];
    DynSmem* sm = reinterpret_cast<DynSmem*>(dsm_raw);

    const int b    = blockIdx.x >> 1;
    const int rank = blockIdx.x & 1;
    const int peer = rank ^ 1;
    const int tid  = threadIdx.x;
    const int lane = tid & 31;
    const int warp = tid >> 5;   // 0..15

    // stage hidden row
    for (int i = tid; i < H_DIM; i += NT) sm->hid[i] = hidden[b * H_DIM + i];

    // ---- phase 1: p partial over this rank's h-half ----
    {
        float local = 0.f;
        for (int h = tid; h < 512; h += NT) {
            const int hh = rank * 512 + h;
            float pa[NDC];
#pragma unroll
            for (int dc = 0; dc < NDC; ++dc)
                pa[dc] = g_dotp[dc * (B_SZ * H_DIM) + b * H_DIM + hh];
            float s = Wp_b[hh];
#pragma unroll
            for (int dc = 0; dc < NDC; ++dc) s += pa[dc];
            local += vp_w[hh] * tanhf(s);
        }
#pragma unroll
        for (int off = 16; off > 0; off >>= 1)
            local += __shfl_down_sync(0xffffffffu, local, off);
        if (lane == 0) sm->wred[warp] = local;
        __syncthreads();
        if (warp == 0) {
            float v = (lane < 16) ? sm->wred[lane] : 0.f;
#pragma unroll
            for (int off = 8; off > 0; off >>= 1)
                v += __shfl_down_sync(0xffffffffu, v, off);
            if (lane == 0) sm->part = v;
        }
    }
    cluster.sync();   // publish part to peer

    if (tid == 0) {
        const float* pp = (const float*)cluster.map_shared_rank((void*)&sm->part, peer);
        float tot = sm->part + *pp + vp_b[0];   // commutative: identical in both ranks
        float p = (float)S_LEN / (1.f + expf(-tot));   // exact expf: feeds round()
        sm->p = p;
        sm->c = (int)rintf(p);                  // round-half-even == jnp.round
    }
    __syncthreads();
    const int   c = sm->c;
    const float p = sm->p;
    const int wbeg = rank * 65;
    const int wend = rank ? W_WIN : 65;

    // precompute gaussian weights
    if (tid < W_WIN) {
        float diff = (float)(c + tid - D_HALF) - p;
        sm->gauss[tid] = __expf(-diff * diff * (1.f / 2048.f));   // stddev=D/2=32
    }
    __syncthreads();

    // ---- phase 2: flash pass, cp.async 2-slot pipeline ----
    {
        const float4* h4 = reinterpret_cast<const float4*>(sm->hid);
        float4 hh[8];
#pragma unroll
        for (int k = 0; k < 8; ++k) hh[k] = h4[k * 32 + lane];

        float4 ctx[8];
#pragma unroll
        for (int k = 0; k < 8; ++k) ctx[k] = make_float4(0.f, 0.f, 0.f, 0.f);
        float m = -1e30f;
        float l = 0.f;

        const uint32_t ring0 = (uint32_t)__cvta_generic_to_shared(&sm->ring[warp][0][lane]);
        const uint32_t slot_stride = 256 * 16;   // 4 KB

        auto prefetch = [&](int w, int slot) {
            const int s = c + w - D_HALF;
            uint32_t dst = ring0 + (uint32_t)slot * slot_stride;
            if (s >= 0 && s < S_LEN) {
                const float4* src = reinterpret_cast<const float4*>(
                    enc + ((size_t)s * B_SZ + b) * H_DIM) + lane;
#pragma unroll
                for (int k = 0; k < 8; ++k)
                    cp_async16(dst + k * 512, src + k * 32);   // 16B per lane
            } else {
                float4 z = make_float4(0.f, 0.f, 0.f, 0.f);
#pragma unroll
                for (int k = 0; k < 8; ++k)
                    sm->ring[warp][slot][k * 32 + lane] = z;   // rare edge rows
            }
            cp_async_commit();   // always commit: wait-group counts stay aligned
        };

        auto compute_row = [&](int w, int slot) {
            const float4* rp = &sm->ring[warp][slot][lane];
            float4 e[8];
#pragma unroll
            for (int k = 0; k < 8; ++k) e[k] = rp[k * 32];   // own-lane data

            float a0 = 0.f, a1 = 0.f, a2 = 0.f, a3 = 0.f;
#pragma unroll
            for (int k = 0; k < 8; ++k) {
                a0 += e[k].x * hh[k].x; a1 += e[k].y * hh[k].y;
                a2 += e[k].z * hh[k].z; a3 += e[k].w * hh[k].w;
            }
            float v = (a0 + a1) + (a2 + a3);
#pragma unroll
            for (int off = 16; off > 0; off >>= 1)
                v += __shfl_xor_sync(0xffffffffu, v, off);   // lane-identical

            if (lane == 0) sm->scores[w] = v;
            float g = sm->gauss[w];

            if (v > m) {                       // warp-uniform, divergence-free
                float scale = __expf(m - v);
                l *= scale;
#pragma unroll
                for (int k = 0; k < 8; ++k) {
                    ctx[k].x *= scale; ctx[k].y *= scale;
                    ctx[k].z *= scale; ctx[k].w *= scale;
                }
                m = v;
            }
            float ew = __expf(v - m);
            l += ew;
            float cw = ew * g;
#pragma unroll
            for (int k = 0; k < 8; ++k) {
                ctx[k].x += cw * e[k].x; ctx[k].y += cw * e[k].y;
                ctx[k].z += cw * e[k].z; ctx[k].w += cw * e[k].w;
            }
        };

        int w = wbeg + warp;
        int slot = 0;
        if (w < wend) prefetch(w, 0);          // prologue
        for (; w < wend; w += 16) {
            const int wn = w + 16;
            if (wn < wend) {
                prefetch(wn, slot ^ 1);        // stream next row during compute
                cp_async_wait<1>();            // current slot complete
            } else {
                cp_async_wait<0>();
            }
            compute_row(w, slot);
            slot ^= 1;
        }

        // publish per-warp state
        if (lane == 0) { sm->m[warp] = m; sm->l[warp] = l; }
#pragma unroll
        for (int k = 0; k < 8; ++k) sm->ctxw[warp][k * 32 + lane] = ctx[k];
    }
    __syncthreads();

    // ---- combine 16 warps within the rank ----
    if (tid == 0) {
        float M = -1e30f;
#pragma unroll
        for (int w2 = 0; w2 < 16; ++w2) M = fmaxf(M, sm->m[w2]);
        float L = 0.f;
#pragma unroll
        for (int w2 = 0; w2 < 16; ++w2) {
            float f = expf(sm->m[w2] - M);
            sm->ef[w2] = f;
            L += sm->l[w2] * f;
        }
        sm->Mrank = M;
        sm->lrank = L;
    }
    __syncthreads();

    // combine into ring[0][0] (free after flash phase)
    float4* ctx_comb = &sm->ring[0][0][0];
    if (tid < 256) {
        float4 o = make_float4(0.f, 0.f, 0.f, 0.f);
#pragma unroll
        for (int w2 = 0; w2 < 16; ++w2) {
            float  f = sm->ef[w2];
            float4 t = sm->ctxw[w2][tid];
            o.x += f * t.x; o.y += f * t.y;
            o.z += f * t.z; o.w += f * t.w;
        }
        ctx_comb[tid] = o;
    }
    cluster.sync();   // publish ctx_comb, Mrank, lrank, scores

    // ---- cross-rank combine + outputs ----
    {
        DynSmem* ps = (DynSmem*)cluster.map_shared_rank((void*)sm, peer);
        const float peerM = ps->Mrank;
        const float peerl = ps->lrank;
        const float Mg = fmaxf(sm->Mrank, peerM);
        const float e_own  = expf(sm->Mrank - Mg);
        const float e_peer = expf(peerM - Mg);
        const float L = sm->lrank * e_own + peerl * e_peer;
        const float invL = 1.f / L;

        // context: own h-half = own-rows ctx + peer-rows ctx, normalized
        if (tid < 128) {
            const int idx = rank * 128 + tid;
            float4 a = ctx_comb[idx];
            float4 q = ps->ring[0][0][idx];     // DSMEM read of peer's combine buffer
            float4 o;
            o.x = (a.x * e_own + q.x * e_peer) * invL;
            o.y = (a.y * e_own + q.y * e_peer) * invL;
            o.z = (a.z * e_own + q.z * e_peer) * invL;
            o.w = (a.w * e_own + q.w * e_peer) * invL;
            reinterpret_cast<float4*>(
                d_out + B_SZ * W_WIN + b * H_DIM + rank * 512)[tid] = o;
        }

        // attn output (rank 0 only): exp(sc - Mg)/L * gauss
        if (rank == 0 && tid < W_WIN) {
            float sc = (tid < 65) ? sm->scores[tid] : ps->scores[tid];
            d_out[b * W_WIN + tid] = __expf(sc - Mg) * invL * sm->gauss[tid];
        }
    }

    cluster.sync();   // no CTA exits while peer may still read its DSMEM
}

// ---------------------------------------------------------------------------
extern "C" void kernel_launch(void* const* d_in, const int* in_sizes, int n_in,
                              void* d_out, int out_size) {
    // metadata order: t, hidden, encoder_outputs, Wp_w, Wp_b, vp_w, vp_b
    const float* hidden = (const float*)d_in[1];
    const float* enc    = (const float*)d_in[2];
    const float* Wp_w   = (const float*)d_in[3];
    const float* Wp_b   = (const float*)d_in[4];
    const float* vp_w   = (const float*)d_in[5];
    const float* vp_b   = (const float*)d_in[6];
    float* out = (float*)d_out;

    // sticky module state; idempotent (first set happens on the uncaptured
    // correctness call, so capture-time behavior is unchanged)
    cudaFuncSetAttribute(k_attn_fused,
                         cudaFuncAttributeMaxDynamicSharedMemorySize,
                         (int)sizeof(DynSmem));

    k_gemm_partial<<<dim3(16, 16), 256>>>(hidden, Wp_w);
    k_attn_fused<<<B_SZ * 2, NT, sizeof(DynSmem)>>>(hidden, enc, Wp_b, vp_w, vp_b, out);
}

// round 15
// speedup vs baseline: 1.0327x; 1.0327x over previous
#include <cuda_runtime.h>
#include <cooperative_groups.h>
#include <math.h>

namespace cg = cooperative_groups;

// Problem constants (fixed shapes)
#define S_LEN 2048
#define B_SZ  64
#define H_DIM 1024
#define D_HALF 64
#define W_WIN 129            // 2*D+1
#define DCH   64             // d-chunk for GEMM partial
#define NDC   (H_DIM / DCH)  // 16
#define NT    512            // fused kernel threads (16 warps; reg cap 128)

// Scratch (allocation-free)
__device__ float g_dotp[NDC * B_SZ * H_DIM];   // [dc][b][h]  4 MB

// ---- packed f32x2 helpers (FFMA2: 2x fp32 FMA throughput, same rounding) ----
__device__ __forceinline__ unsigned long long pk2(float lo, float hi) {
    unsigned long long r;
    asm("mov.b64 %0, {%1, %2};" : "=l"(r) : "f"(lo), "f"(hi));
    return r;
}
__device__ __forceinline__ void fma2(unsigned long long& d,
                                     unsigned long long a, unsigned long long b) {
    asm("fma.rn.f32x2 %0, %1, %2, %0;" : "+l"(d) : "l"(a), "l"(b));
}
__device__ __forceinline__ void upk2(unsigned long long v, float& lo, float& hi) {
    asm("mov.b64 {%0, %1}, %2;" : "=f"(lo), "=f"(hi) : "l"(v));
}

// ---------------------------------------------------------------------------
// K1: partial GEMM via FFMA2.  dotp[dc][b][h] = sum_d hidden[b][d]*Wp_w[h][d]
// fp32 semantics preserved exactly: p feeds round() -> window center.
// ---------------------------------------------------------------------------
__global__ __launch_bounds__(256, 2)
void k_gemm_partial(const float* __restrict__ hidden,
                    const float* __restrict__ Wp_w) {
    const int h0 = blockIdx.x * 64;
    const int dc = blockIdx.y;
    const int d0 = dc * DCH;

    __shared__ float sh_ht[DCH][66];  // [d][b] padded (b contiguous)
    __shared__ float sh_w[DCH][65];   // [d][h] padded

    const int tid  = threadIdx.x;
    const int lane = tid & 31;
    const int warp = tid >> 5;

    for (int idx = tid; idx < 64 * 16; idx += 256) {
        int b  = idx >> 4;
        int dq = (idx & 15) << 2;
        float4 v = *reinterpret_cast<const float4*>(&hidden[b * H_DIM + d0 + dq]);
        sh_ht[dq + 0][b] = v.x; sh_ht[dq + 1][b] = v.y;
        sh_ht[dq + 2][b] = v.z; sh_ht[dq + 3][b] = v.w;
    }
    for (int idx = tid; idx < 64 * 16; idx += 256) {
        int h  = idx >> 4;
        int dq = (idx & 15) << 2;
        float4 v = *reinterpret_cast<const float4*>(&Wp_w[(size_t)(h0 + h) * H_DIM + d0 + dq]);
        sh_w[dq + 0][h] = v.x; sh_w[dq + 1][h] = v.y;
        sh_w[dq + 2][h] = v.z; sh_w[dq + 3][h] = v.w;
    }
    __syncthreads();

    const int hl = lane & 15;
    const int bl = ((lane >> 4) << 2) + (warp << 3);   // multiple of 4 -> LDS.64 aligned

    unsigned long long acc2[2][4] = {};
#pragma unroll 16
    for (int d = 0; d < DCH; ++d) {
        float wv0 = sh_w[d][hl];
        float wv1 = sh_w[d][hl + 16];
        float wv2 = sh_w[d][hl + 32];
        float wv3 = sh_w[d][hl + 48];
        unsigned long long wp0 = pk2(wv0, wv0);
        unsigned long long wp1 = pk2(wv1, wv1);
        unsigned long long wp2 = pk2(wv2, wv2);
        unsigned long long wp3 = pk2(wv3, wv3);
        unsigned long long h01 = *reinterpret_cast<const unsigned long long*>(&sh_ht[d][bl]);
        unsigned long long h23 = *reinterpret_cast<const unsigned long long*>(&sh_ht[d][bl + 2]);
        fma2(acc2[0][0], h01, wp0); fma2(acc2[0][1], h01, wp1);
        fma2(acc2[0][2], h01, wp2); fma2(acc2[0][3], h01, wp3);
        fma2(acc2[1][0], h23, wp0); fma2(acc2[1][1], h23, wp1);
        fma2(acc2[1][2], h23, wp2); fma2(acc2[1][3], h23, wp3);
    }

    float* outp = &g_dotp[(size_t)dc * (B_SZ * H_DIM)];
#pragma unroll
    for (int r = 0; r < 2; ++r) {
#pragma unroll
        for (int i = 0; i < 4; ++i) {
            float lo, hi;
            upk2(acc2[r][i], lo, hi);
            int h = h0 + hl + 16 * i;
            outp[(bl + 2 * r + 0) * H_DIM + h] = lo;
            outp[(bl + 2 * r + 1) * H_DIM + h] = hi;
        }
    }
}

// ---------------------------------------------------------------------------
// K2 (fused, clustered, flash + bulk-async pipeline): 2 CTAs per b,
// 128 blocks, 512 threads. Per-warp 2-slot smem ring filled by
// cp.async.bulk (UBLKCP: ONE instruction per 4KB row, bypasses L1tex
// wavefront queue), completion via per-slot mbarriers.
// ring[0] is reused as the combine buffer after the flash phase.
// ---------------------------------------------------------------------------
struct DynSmem {
    float4 ring[16][2][256];      // per-warp 2-slot row ring   (128 KB)
    float4 ctxw[16][256];         // per-warp ctx accumulators   (64 KB)
    float  hid[H_DIM];            // hidden row                   (4 KB)
    unsigned long long mbar[16][2];  // per-warp per-slot mbarriers
    float  scores[W_WIN];
    float  gauss[W_WIN];
    float  m[16];
    float  l[16];
    float  ef[16];
    float  wred[16];
    float  part;
    float  p;
    int    c;
    float  Mrank;
    float  lrank;
};

__device__ __forceinline__ void mbar_init(uint32_t mbar, uint32_t count) {
    asm volatile("mbarrier.init.shared.b64 [%0], %1;" :: "r"(mbar), "r"(count) : "memory");
}
__device__ __forceinline__ void mbar_expect_tx(uint32_t mbar, uint32_t bytes) {
    asm volatile("mbarrier.arrive.expect_tx.shared.b64 _, [%0], %1;"
                 :: "r"(mbar), "r"(bytes) : "memory");
}
__device__ __forceinline__ void mbar_wait(uint32_t mbar, uint32_t parity) {
    uint32_t done;
    asm volatile(
        "{\n\t.reg .pred p;\n\t"
        "mbarrier.try_wait.parity.acquire.cta.shared::cta.b64 p, [%1], %2;\n\t"
        "selp.b32 %0, 1, 0, p;\n\t}"
        : "=r"(done) : "r"(mbar), "r"(parity) : "memory");
    if (!done) {
        asm volatile(
            "{\n\t.reg .pred P1;\n\t"
            "WAIT_LOOP_%=:\n\t"
            "mbarrier.try_wait.parity.acquire.cta.shared::cta.b64 P1, [%0], %1, 0x989680;\n\t"
            "@P1 bra.uni WAIT_DONE_%=;\n\t"
            "bra.uni WAIT_LOOP_%=;\n\t"
            "WAIT_DONE_%=:\n\t}"
            :: "r"(mbar), "r"(parity) : "memory");
    }
}
__device__ __forceinline__ void bulk_copy_g2s(uint32_t dst_smem, const void* src,
                                              uint32_t bytes, uint32_t mbar) {
    asm volatile(
        "cp.async.bulk.shared::cta.global.mbarrier::complete_tx::bytes [%0], [%1], %2, [%3];"
        :: "r"(dst_smem), "l"(src), "r"(bytes), "r"(mbar) : "memory");
}

__global__ __launch_bounds__(NT, 1) __cluster_dims__(2, 1, 1)
void k_attn_fused(const float* __restrict__ hidden,
                  const float* __restrict__ enc,
                  const float* __restrict__ Wp_b,
                  const float* __restrict__ vp_w,
                  const float* __restrict__ vp_b,
                  float* __restrict__ d_out) {
    cg::cluster_group cluster = cg::this_cluster();
    extern __shared__ __align__(16) char dsm_raw[];
    DynSmem* sm = reinterpret_cast<DynSmem*>(dsm_raw);

    const int b    = blockIdx.x >> 1;
    const int rank = blockIdx.x & 1;
    const int peer = rank ^ 1;
    const int tid  = threadIdx.x;
    const int lane = tid & 31;
    const int warp = tid >> 5;   // 0..15

    // init per-warp mbarriers (arrive count 1: expect_tx thread)
    if (tid < 32) {
        uint32_t mb = (uint32_t)__cvta_generic_to_shared(&sm->mbar[tid >> 1][tid & 1]);
        mbar_init(mb, 1);
    }
    // stage hidden row
    for (int i = tid; i < H_DIM; i += NT) sm->hid[i] = hidden[b * H_DIM + i];

    // ---- phase 1: p partial over this rank's h-half ----
    {
        float local = 0.f;
        for (int h = tid; h < 512; h += NT) {
            const int hh = rank * 512 + h;
            float pa[NDC];
#pragma unroll
            for (int dc = 0; dc < NDC; ++dc)
                pa[dc] = g_dotp[dc * (B_SZ * H_DIM) + b * H_DIM + hh];
            float s = Wp_b[hh];
#pragma unroll
            for (int dc = 0; dc < NDC; ++dc) s += pa[dc];
            local += vp_w[hh] * tanhf(s);
        }
#pragma unroll
        for (int off = 16; off > 0; off >>= 1)
            local += __shfl_down_sync(0xffffffffu, local, off);
        if (lane == 0) sm->wred[warp] = local;
        __syncthreads();     // also orders mbar_init before any use
        if (warp == 0) {
            float v = (lane < 16) ? sm->wred[lane] : 0.f;
#pragma unroll
            for (int off = 8; off > 0; off >>= 1)
                v += __shfl_down_sync(0xffffffffu, v, off);
            if (lane == 0) sm->part = v;
        }
    }
    cluster.sync();   // publish part to peer

    if (tid == 0) {
        const float* pp = (const float*)cluster.map_shared_rank((void*)&sm->part, peer);
        float tot = sm->part + *pp + vp_b[0];   // commutative: identical in both ranks
        float p = (float)S_LEN / (1.f + expf(-tot));   // exact expf: feeds round()
        sm->p = p;
        sm->c = (int)rintf(p);                  // round-half-even == jnp.round
    }
    __syncthreads();
    const int   c = sm->c;
    const float p = sm->p;
    const int wbeg = rank * 65;
    const int wend = rank ? W_WIN : 65;

    // precompute gaussian weights
    if (tid < W_WIN) {
        float diff = (float)(c + tid - D_HALF) - p;
        sm->gauss[tid] = __expf(-diff * diff * (1.f / 2048.f));   // stddev=D/2=32
    }
    __syncthreads();

    // ---- phase 2: flash pass, bulk-async 2-slot pipeline ----
    {
        const float4* h4 = reinterpret_cast<const float4*>(sm->hid);
        float4 hh[8];
#pragma unroll
        for (int k = 0; k < 8; ++k) hh[k] = h4[k * 32 + lane];

        float4 ctx[8];
#pragma unroll
        for (int k = 0; k < 8; ++k) ctx[k] = make_float4(0.f, 0.f, 0.f, 0.f);
        float m = -1e30f;
        float l = 0.f;

        const uint32_t ring_base =
            (uint32_t)__cvta_generic_to_shared(&sm->ring[warp][0][0]);
        const uint32_t mb0 = (uint32_t)__cvta_generic_to_shared(&sm->mbar[warp][0]);
        const uint32_t mb1 = mb0 + 8;
        int phase0 = 0, phase1 = 0;

        // issue: one UBLKCP per in-range row (lane 0 only)
        auto issue = [&](int w, int slot) -> bool {
            const int s = c + w - D_HALF;
            if (s < 0 || s >= S_LEN) return false;
            if (lane == 0) {
                uint32_t mb = slot ? mb1 : mb0;
                mbar_expect_tx(mb, 4096);
                bulk_copy_g2s(ring_base + (uint32_t)slot * 4096,
                              enc + ((size_t)s * B_SZ + b) * H_DIM, 4096, mb);
            }
            return true;
        };

        auto consume = [&](int w, int slot, bool loaded) {
            float4 e[8];
            if (loaded) {
                if (slot) { mbar_wait(mb1, phase1); phase1 ^= 1; }
                else      { mbar_wait(mb0, phase0); phase0 ^= 1; }
                const float4* rp = &sm->ring[warp][slot][lane];
#pragma unroll
                for (int k = 0; k < 8; ++k) e[k] = rp[k * 32];
            } else {
#pragma unroll
                for (int k = 0; k < 8; ++k) e[k] = make_float4(0.f, 0.f, 0.f, 0.f);
            }

            float a0 = 0.f, a1 = 0.f, a2 = 0.f, a3 = 0.f;
#pragma unroll
            for (int k = 0; k < 8; ++k) {
                a0 += e[k].x * hh[k].x; a1 += e[k].y * hh[k].y;
                a2 += e[k].z * hh[k].z; a3 += e[k].w * hh[k].w;
            }
            float v = (a0 + a1) + (a2 + a3);
#pragma unroll
            for (int off = 16; off > 0; off >>= 1)
                v += __shfl_xor_sync(0xffffffffu, v, off);   // lane-identical

            if (lane == 0) sm->scores[w] = v;
            float g = sm->gauss[w];

            if (v > m) {                       // warp-uniform, divergence-free
                float scale = __expf(m - v);
                l *= scale;
#pragma unroll
                for (int k = 0; k < 8; ++k) {
                    ctx[k].x *= scale; ctx[k].y *= scale;
                    ctx[k].z *= scale; ctx[k].w *= scale;
                }
                m = v;
            }
            float ew = __expf(v - m);
            l += ew;
            float cw = ew * g;
#pragma unroll
            for (int k = 0; k < 8; ++k) {
                ctx[k].x += cw * e[k].x; ctx[k].y += cw * e[k].y;
                ctx[k].z += cw * e[k].z; ctx[k].w += cw * e[k].w;
            }
        };

        int w = wbeg + warp;
        int slot = 0;
        bool curLoaded = (w < wend) ? issue(w, 0) : false;
        for (; w < wend; w += 16) {
            const int wn = w + 16;
            bool nextLoaded = (wn < wend) ? issue(wn, slot ^ 1) : false;
            consume(w, slot, curLoaded);
            curLoaded = nextLoaded;
            slot ^= 1;
        }

        // publish per-warp state
        if (lane == 0) { sm->m[warp] = m; sm->l[warp] = l; }
#pragma unroll
        for (int k = 0; k < 8; ++k) sm->ctxw[warp][k * 32 + lane] = ctx[k];
    }
    __syncthreads();

    // ---- combine 16 warps within the rank ----
    if (tid == 0) {
        float M = -1e30f;
#pragma unroll
        for (int w2 = 0; w2 < 16; ++w2) M = fmaxf(M, sm->m[w2]);
        float L = 0.f;
#pragma unroll
        for (int w2 = 0; w2 < 16; ++w2) {
            float f = expf(sm->m[w2] - M);
            sm->ef[w2] = f;
            L += sm->l[w2] * f;
        }
        sm->Mrank = M;
        sm->lrank = L;
    }
    __syncthreads();

    // combine into ring[0][0] (free after flash phase)
    float4* ctx_comb = &sm->ring[0][0][0];
    if (tid < 256) {
        float4 o = make_float4(0.f, 0.f, 0.f, 0.f);
#pragma unroll
        for (int w2 = 0; w2 < 16; ++w2) {
            float  f = sm->ef[w2];
            float4 t = sm->ctxw[w2][tid];
            o.x += f * t.x; o.y += f * t.y;
            o.z += f * t.z; o.w += f * t.w;
        }
        ctx_comb[tid] = o;
    }
    cluster.sync();   // publish ctx_comb, Mrank, lrank, scores

    // ---- cross-rank combine + outputs ----
    {
        DynSmem* ps = (DynSmem*)cluster.map_shared_rank((void*)sm, peer);
        const float peerM = ps->Mrank;
        const float peerl = ps->lrank;
        const float Mg = fmaxf(sm->Mrank, peerM);
        const float e_own  = expf(sm->Mrank - Mg);
        const float e_peer = expf(peerM - Mg);
        const float L = sm->lrank * e_own + peerl * e_peer;
        const float invL = 1.f / L;

        // context: own h-half = own-rows ctx + peer-rows ctx, normalized
        if (tid < 128) {
            const int idx = rank * 128 + tid;
            float4 a = ctx_comb[idx];
            float4 q = ps->ring[0][0][idx];     // DSMEM read of peer's combine buffer
            float4 o;
            o.x = (a.x * e_own + q.x * e_peer) * invL;
            o.y = (a.y * e_own + q.y * e_peer) * invL;
            o.z = (a.z * e_own + q.z * e_peer) * invL;
            o.w = (a.w * e_own + q.w * e_peer) * invL;
            reinterpret_cast<float4*>(
                d_out + B_SZ * W_WIN + b * H_DIM + rank * 512)[tid] = o;
        }

        // attn output (rank 0 only): exp(sc - Mg)/L * gauss
        if (rank == 0 && tid < W_WIN) {
            float sc = (tid < 65) ? sm->scores[tid] : ps->scores[tid];
            d_out[b * W_WIN + tid] = __expf(sc - Mg) * invL * sm->gauss[tid];
        }
    }

    cluster.sync();   // no CTA exits while peer may still read its DSMEM
}

// ---------------------------------------------------------------------------
extern "C" void kernel_launch(void* const* d_in, const int* in_sizes, int n_in,
                              void* d_out, int out_size) {
    // metadata order: t, hidden, encoder_outputs, Wp_w, Wp_b, vp_w, vp_b
    const float* hidden = (const float*)d_in[1];
    const float* enc    = (const float*)d_in[2];
    const float* Wp_w   = (const float*)d_in[3];
    const float* Wp_b   = (const float*)d_in[4];
    const float* vp_w   = (const float*)d_in[5];
    const float* vp_b   = (const float*)d_in[6];
    float* out = (float*)d_out;

    // sticky module state; idempotent (first set happens on the uncaptured
    // correctness call, so capture-time behavior is unchanged)
    cudaFuncSetAttribute(k_attn_fused,
                         cudaFuncAttributeMaxDynamicSharedMemorySize,
                         (int)sizeof(DynSmem));

    k_gemm_partial<<<dim3(16, 16), 256>>>(hidden, Wp_w);
    k_attn_fused<<<B_SZ * 2, NT, sizeof(DynSmem)>>>(hidden, enc, Wp_b, vp_w, vp_b, out);
}